// round 12
// baseline (speedup 1.0000x reference)
#include <cuda_runtime.h>
#include <cuda_bf16.h>
#include <stdint.h>

// ---------------------------------------------------------------------------
// Exact Chamfer via uniform-grid NN, v9: G=32 bucket grid + full shell table.
//   2 launches: [scatter + table build + lastCTA count-pack] ->
//               [query + lastCTA reduce].
//   G=32 (cell 0.25 over [-4,4]^3): ~16 pts in densest cells. Shell table:
//   63^3 offsets grouped by Chebyshev r (closed-form rank, deterministic).
//   Query (warp per query, 1024-thread CTAs): SMEM-staged byte counts +
//   r<=6 shell table; shells enumerated 32 offsets/pass (bounds, cnt>0,
//   exact box-dist < per-lane cur; edge cells extend to infinity so clamped
//   outliers are exact); survivor cells scanned lane-strided (x2 unroll);
//   per-lane cur within shell (any lane's cur >= true min -> pruning safe),
//   butterfly-min at shell boundary; break ((r-1)*cell)^2 >= cur.
//   Exact NN; fp-min order-independent + fixed-order reduce -> deterministic.
// ---------------------------------------------------------------------------

#define NPTS   16384
#define G      32
#define NC     (G*G*G)          // 32768 cells per array
#define CELLF  0.25f
#define GMINF  (-4.0f)
#define INVC   4.0f
#define CAP    64
#define NCTA_Q 1024
#define TABN   250047           // 63^3 offsets (r <= 31)
#define TAB_S  2197             // 13^3 = shells r <= 6 cached in SMEM

__device__ int           g_n[2 * NC];     // zero at load; re-zeroed by query
__device__ unsigned char g_n8[2 * NC];    // packed counts (scatter lastCTA)
__device__ float4        g_bkt[2 * NC * CAP];
__device__ float         g_dmin[2 * NPTS];
__device__ int           g_tab[TABN];     // (dx+31)|(dy+31)<<6|(dz+31)<<12
__device__ unsigned int  g_c1, g_c2;      // last-CTA counters (self-reset)

__device__ __forceinline__ int cell_of(float v) {
    int c = (int)floorf((v - GMINF) * INVC);
    return min(G - 1, max(0, c));
}
__device__ __forceinline__ float axis_bd(float q, int X) {
    const float lo = GMINF + X * CELLF, hi = lo + CELLF;
    float b = 0.f;
    if (q < lo)      { if (X > 0)     b = lo - q; }
    else if (q > hi) { if (X < G - 1) b = q - hi; }
    return b;
}
__device__ __forceinline__ int shell_base(int r) {   // (2r-1)^3, 0 @ r=0
    const int m = 2 * r - 1;
    return (r == 0) ? 0 : m * m * m;
}

// --------- scatter + analytic table build + lastCTA count pack -------------
__global__ __launch_bounds__(1024)
void scatter_kernel(const float* __restrict__ pa, const float* __restrict__ pb) {
    const int t = blockIdx.x * 1024 + threadIdx.x;   // 32 CTAs -> 0..32767
    const int arr = t >> 14, i = t & (NPTS - 1);
    const float* s = arr ? pb : pa;
    const float x = s[3 * i + 0], y = s[3 * i + 1], z = s[3 * i + 2];
    const int ci = (cell_of(z) * G + cell_of(y)) * G + cell_of(x);
    const int pos = atomicAdd(&g_n[arr * NC + ci], 1);
    if (pos < CAP)
        g_bkt[(arr * NC + ci) * CAP + pos] = make_float4(x, y, z, 0.f);

    for (int e = t; e < TABN; e += 32768) {   // deterministic shell table
        const int dz = e / 3969 - 31;         // 63*63
        const int rm = e % 3969;
        const int dy = rm / 63 - 31;
        const int dx = rm % 63 - 31;
        const int r = max(abs(dx), max(abs(dy), abs(dz)));
        int rank = 0;
        if (r > 0) {
            const int w1 = 2 * r + 1, w0 = 2 * r - 1;
            if (abs(dz) == r) {
                rank = ((dz == r) ? 0 : w1 * w1) + (dy + r) * w1 + (dx + r);
            } else if (abs(dy) == r) {
                rank = 2 * w1 * w1 + ((dy == r) ? 0 : w1 * w0)
                     + (dz + r - 1) * w1 + (dx + r);
            } else {
                rank = 2 * w1 * w1 + 2 * w1 * w0 + ((dx == r) ? 0 : w0 * w0)
                     + (dz + r - 1) * w0 + (dy + r - 1);
            }
        }
        g_tab[shell_base(r) + rank] =
            (dx + 31) | ((dy + 31) << 6) | ((dz + 31) << 12);
    }

    // ---- last CTA packs counts to bytes (fence->sync->vote->fence) ----
    __threadfence();
    __syncthreads();
    __shared__ unsigned s_last;
    if (threadIdx.x == 0) s_last = (atomicAdd(&g_c1, 1u) == 31u);
    __syncthreads();
    if (!s_last) return;
    __threadfence();
    if (threadIdx.x == 0) g_c1 = 0u;

    const int4* __restrict__ gn4 = (const int4*)g_n;
    uchar4* __restrict__ n84 = (uchar4*)g_n8;
    for (int k = threadIdx.x; k < 2 * NC / 4; k += 1024) {
        const int4 v = __ldcg(&gn4[k]);
        n84[k] = make_uchar4((unsigned char)min(v.x, CAP),
                             (unsigned char)min(v.y, CAP),
                             (unsigned char)min(v.z, CAP),
                             (unsigned char)min(v.w, CAP));
    }
}

// ---------------------- query + lastCTA reduce ------------------------------
__global__ __launch_bounds__(1024, 2)
void query_kernel(const float* __restrict__ pa, const float* __restrict__ pb,
                  float* __restrict__ out) {
    __shared__ unsigned char s_cnt[NC];   // opposite array's counts (32 KB)
    __shared__ int s_tab[TAB_S];          // shell offsets r<=6 (8.8 KB)
    const unsigned full = 0xffffffffu;
    const int w    = blockIdx.x * 32 + (threadIdx.x >> 5);  // 0..32767
    const int lane = threadIdx.x & 31;
    const int arr  = w >> 14;                               // CTA-uniform
    const int i    = w & (NPTS - 1);

    {   // stage SMEM tables
        const int4* __restrict__ gc = (const int4*)&g_n8[(1 - arr) * NC];
        int4* sc4 = (int4*)s_cnt;
        for (int k = threadIdx.x; k < NC / 16; k += 1024) sc4[k] = __ldg(&gc[k]);
        for (int k = threadIdx.x; k < TAB_S; k += 1024)
            s_tab[k] = __ldg(&g_tab[k]);
    }
    __syncthreads();

    const float* s = arr ? pb : pa;
    const float qx = s[3 * i + 0], qy = s[3 * i + 1], qz = s[3 * i + 2];
    const int cx = cell_of(qx), cy = cell_of(qy), cz = cell_of(qz);
    const float4* __restrict__ bkt = &g_bkt[(1 - arr) * NC * CAP];

    float cur = 3e38f;                    // warp-uniform at shell boundaries

    for (int r = 0; r < G; ++r) {
        if (r >= 1) {
            const float lb = (float)(r - 1) * CELLF;
            if (lb * lb >= cur) break;    // cur uniform here
        }
        const int base = shell_base(r);
        const int size = shell_base(r + 1) - base;

        for (int pass = 0; pass < size; pass += 32) {
            const int idx = pass + lane;
            int ci = 0, cnt = 0;
            float bd2 = 3e38f;
            if (idx < size) {
                const int a = base + idx;
                const int e = (a < TAB_S) ? s_tab[a] : __ldg(&g_tab[a]);
                const int X = cx + (e & 63) - 31;
                const int Y = cy + ((e >> 6) & 63) - 31;
                const int Z = cz + ((e >> 12) & 63) - 31;
                if (((unsigned)X < G) & ((unsigned)Y < G) & ((unsigned)Z < G)) {
                    ci = (Z * G + Y) * G + X;
                    cnt = s_cnt[ci];
                    if (cnt > 0) {
                        const float bx = axis_bd(qx, X);
                        const float by = axis_bd(qy, Y);
                        const float bz = axis_bd(qz, Z);
                        bd2 = fmaf(bx, bx, fmaf(by, by, bz * bz));
                    }
                }
            }
            unsigned mask = __ballot_sync(full, bd2 < cur);  // per-lane cur: safe
            while (mask) {
                const int src = __ffs(mask) - 1;
                mask &= mask - 1;
                const int ci_s  = __shfl_sync(full, ci, src);
                const int cnt_s = __shfl_sync(full, cnt, src);
                const float4* __restrict__ cp = &bkt[ci_s * CAP];
                int u = lane;
                for (; u + 32 < cnt_s; u += 64) {
                    const float4 p0 = __ldg(&cp[u]);
                    const float4 p1 = __ldg(&cp[u + 32]);
                    const float dx0 = qx - p0.x, dy0 = qy - p0.y, dz0 = qz - p0.z;
                    const float dx1 = qx - p1.x, dy1 = qy - p1.y, dz1 = qz - p1.z;
                    cur = fminf(cur, fmaf(dx0, dx0, fmaf(dy0, dy0, dz0 * dz0)));
                    cur = fminf(cur, fmaf(dx1, dx1, fmaf(dy1, dy1, dz1 * dz1)));
                }
                if (u < cnt_s) {
                    const float4 p0 = __ldg(&cp[u]);
                    const float dx0 = qx - p0.x, dy0 = qy - p0.y, dz0 = qz - p0.z;
                    cur = fminf(cur, fmaf(dx0, dx0, fmaf(dy0, dy0, dz0 * dz0)));
                }
            }
        }
        // shell-boundary butterfly: restore warp-uniform cur
        #pragma unroll
        for (int o = 16; o; o >>= 1)
            cur = fminf(cur, __shfl_xor_sync(full, cur, o));
    }
    if (lane == 0) g_dmin[w] = cur;

    // ---- last-CTA fixed-order reduce (fence -> sync -> vote -> fence) ----
    __threadfence();
    __syncthreads();
    __shared__ unsigned s_last;
    if (threadIdx.x == 0) s_last = (atomicAdd(&g_c2, 1u) == NCTA_Q - 1u);
    __syncthreads();
    if (!s_last) return;
    __threadfence();
    if (threadIdx.x == 0) g_c2 = 0u;

    __shared__ double sm[1024];
    const int tid = threadIdx.x;
    double acc = 0.0;
    for (int k = tid; k < 2 * NPTS; k += 1024)
        acc += (double)__ldcg(&g_dmin[k]);
    sm[tid] = acc;
    __syncthreads();
    for (int o = 512; o; o >>= 1) {
        if (tid < o) sm[tid] += sm[tid + o];
        __syncthreads();
    }
    if (tid == 0) out[0] = (float)(sm[0] * (1.0 / (double)NPTS));

    // re-zero bucket counts for next graph replay
    int4* gn4 = (int4*)g_n;
    const int4 z4 = make_int4(0, 0, 0, 0);
    for (int k = tid; k < 2 * NC / 4; k += 1024) gn4[k] = z4;
}

extern "C" void kernel_launch(void* const* d_in, const int* in_sizes, int n_in,
                              void* d_out, int out_size) {
    const float* p_hat = (const float*)d_in[0];  // [16384,3]
    const float* p     = (const float*)d_in[1];  // [16384,3]
    float* out = (float*)d_out;

    scatter_kernel<<<32, 1024>>>(p_hat, p);
    query_kernel<<<NCTA_Q, 1024>>>(p_hat, p, out);
}

// round 13
// speedup vs baseline: 1.4105x; 1.4105x over previous
#include <cuda_runtime.h>
#include <cuda_bf16.h>
#include <stdint.h>

// ---------------------------------------------------------------------------
// Exact Chamfer via uniform-grid NN, v10 = best measured pieces composed:
//   G=16 bucket grid (v7 query engine, NO SMEM staging — staging measured as
//   ~8M extra warp-instrs in R11) + atomic-free analytic shell table (v8
//   scatter) + byte-packed counts + per-lane cur within shells (butterfly
//   only at shell boundaries) + x2-unrolled candidate scan.
//   2 launches: [scatter + table + lastCTA count-pack] ->
//               [query + lastCTA reduce + g_n re-zero].
//   Exactness: per-cell exact box-distance pruning (edge cells extend to
//   infinity -> clamped outliers exact); per-lane cur is an achieved
//   distance >= true min so pruning/break stay conservative; shell break
//   ((r-1)*cell)^2 >= cur after butterfly (warp-uniform). fp-min is
//   order-independent; fixed-order double reduce -> deterministic output.
// ---------------------------------------------------------------------------

#define NPTS   16384
#define G      16
#define NC     (G*G*G)          // 4096 cells per array
#define CELLF  0.5f
#define GMINF  (-4.0f)
#define INVC   2.0f
#define CAP    192
#define NCTA_Q 4096
#define TABN   29791            // 31^3 offsets (r <= 15)

__device__ int           g_n[2 * NC];     // zero at load; re-zeroed by query
__device__ unsigned char g_n8[2 * NC];    // byte counts (scatter lastCTA)
__device__ float4        g_bkt[2 * NC * CAP];
__device__ float         g_dmin[2 * NPTS];
__device__ int           g_tab[TABN];     // (dx+15)|(dy+15)<<5|(dz+15)<<10
__device__ unsigned int  g_c1, g_c2;      // last-CTA counters (self-reset)

__device__ __forceinline__ int cell_of(float v) {
    int c = (int)floorf((v - GMINF) * INVC);
    return min(G - 1, max(0, c));
}
__device__ __forceinline__ float axis_bd(float q, int X) {
    const float lo = GMINF + X * CELLF, hi = lo + CELLF;
    float b = 0.f;
    if (q < lo)      { if (X > 0)     b = lo - q; }
    else if (q > hi) { if (X < G - 1) b = q - hi; }
    return b;
}
__device__ __forceinline__ int shell_base(int r) {   // (2r-1)^3, 0 @ r=0
    const int m = 2 * r - 1;
    return (r == 0) ? 0 : m * m * m;
}

// --------- scatter + analytic table build + lastCTA count pack -------------
__global__ __launch_bounds__(1024)
void scatter_kernel(const float* __restrict__ pa, const float* __restrict__ pb) {
    const int t = blockIdx.x * 1024 + threadIdx.x;   // 32 CTAs -> 0..32767
    const int arr = t >> 14, i = t & (NPTS - 1);
    const float* s = arr ? pb : pa;
    const float x = s[3 * i + 0], y = s[3 * i + 1], z = s[3 * i + 2];
    const int ci = (cell_of(z) * G + cell_of(y)) * G + cell_of(x);
    const int pos = atomicAdd(&g_n[arr * NC + ci], 1);
    if (pos < CAP)
        g_bkt[(arr * NC + ci) * CAP + pos] = make_float4(x, y, z, 0.f);

    if (t < TABN) {   // deterministic closed-form rank within shell r
        const int dz = t / 961 - 15;
        const int rm = t % 961;
        const int dy = rm / 31 - 15;
        const int dx = rm % 31 - 15;
        const int r = max(abs(dx), max(abs(dy), abs(dz)));
        int rank = 0;
        if (r > 0) {
            const int w1 = 2 * r + 1, w0 = 2 * r - 1;
            if (abs(dz) == r) {                       // z-faces
                rank = ((dz == r) ? 0 : w1 * w1) + (dy + r) * w1 + (dx + r);
            } else if (abs(dy) == r) {                // y-faces
                rank = 2 * w1 * w1 + ((dy == r) ? 0 : w1 * w0)
                     + (dz + r - 1) * w1 + (dx + r);
            } else {                                  // x-faces
                rank = 2 * w1 * w1 + 2 * w1 * w0 + ((dx == r) ? 0 : w0 * w0)
                     + (dz + r - 1) * w0 + (dy + r - 1);
            }
        }
        g_tab[shell_base(r) + rank] =
            (dx + 15) | ((dy + 15) << 5) | ((dz + 15) << 10);
    }

    // ---- last CTA packs counts to bytes (fence->sync->vote->fence) ----
    __threadfence();
    __syncthreads();
    __shared__ unsigned s_last;
    if (threadIdx.x == 0) s_last = (atomicAdd(&g_c1, 1u) == 31u);
    __syncthreads();
    if (!s_last) return;
    __threadfence();
    if (threadIdx.x == 0) g_c1 = 0u;

    const int4* __restrict__ gn4 = (const int4*)g_n;
    uchar4* __restrict__ n84 = (uchar4*)g_n8;
    for (int k = threadIdx.x; k < 2 * NC / 4; k += 1024) {
        const int4 v = __ldcg(&gn4[k]);
        n84[k] = make_uchar4((unsigned char)min(v.x, CAP),
                             (unsigned char)min(v.y, CAP),
                             (unsigned char)min(v.z, CAP),
                             (unsigned char)min(v.w, CAP));
    }
}

// ---------------------- query + lastCTA reduce ------------------------------
__global__ __launch_bounds__(256)
void query_kernel(const float* __restrict__ pa, const float* __restrict__ pb,
                  float* __restrict__ out) {
    const unsigned full = 0xffffffffu;
    const int w    = blockIdx.x * 8 + (threadIdx.x >> 5);   // 0..32767
    const int lane = threadIdx.x & 31;
    const int arr  = w >> 14;
    const int i    = w & (NPTS - 1);
    const float* s = arr ? pb : pa;
    const float qx = s[3 * i + 0], qy = s[3 * i + 1], qz = s[3 * i + 2];
    const int cx = cell_of(qx), cy = cell_of(qy), cz = cell_of(qz);
    const unsigned char* __restrict__ cnts = &g_n8[(1 - arr) * NC];
    const float4* __restrict__ bkt = &g_bkt[(1 - arr) * NC * CAP];

    float cur = 3e38f;      // per-lane inside shells; warp-uniform at boundary

    for (int r = 0; r < 16; ++r) {
        if (r >= 1) {
            const float lb = (float)(r - 1) * CELLF;
            if (lb * lb >= cur) break;    // cur uniform here
        }
        const int base = shell_base(r);
        const int size = shell_base(r + 1) - base;

        for (int pass = 0; pass < size; pass += 32) {
            const int idx = pass + lane;
            int ci = 0, cnt = 0;
            float bd2 = 3e38f;
            if (idx < size) {
                const int e = __ldg(&g_tab[base + idx]);
                const int X = cx + (e & 31) - 15;
                const int Y = cy + ((e >> 5) & 31) - 15;
                const int Z = cz + ((e >> 10) & 31) - 15;
                if (((unsigned)X < G) & ((unsigned)Y < G) & ((unsigned)Z < G)) {
                    ci = (Z * G + Y) * G + X;
                    cnt = __ldg(&cnts[ci]);
                    if (cnt > 0) {
                        const float bx = axis_bd(qx, X);
                        const float by = axis_bd(qy, Y);
                        const float bz = axis_bd(qz, Z);
                        bd2 = fmaf(bx, bx, fmaf(by, by, bz * bz));
                    }
                }
            }
            unsigned mask = __ballot_sync(full, bd2 < cur);  // per-lane cur: safe
            while (mask) {
                const int src = __ffs(mask) - 1;
                mask &= mask - 1;
                const int ci_s  = __shfl_sync(full, ci, src);
                const int cnt_s = __shfl_sync(full, cnt, src);
                const float4* __restrict__ cp = &bkt[ci_s * CAP];
                int u = lane;
                for (; u + 32 < cnt_s; u += 64) {      // 2 loads in flight
                    const float4 p0 = __ldg(&cp[u]);
                    const float4 p1 = __ldg(&cp[u + 32]);
                    const float dx0 = qx - p0.x, dy0 = qy - p0.y, dz0 = qz - p0.z;
                    const float dx1 = qx - p1.x, dy1 = qy - p1.y, dz1 = qz - p1.z;
                    cur = fminf(cur, fmaf(dx0, dx0, fmaf(dy0, dy0, dz0 * dz0)));
                    cur = fminf(cur, fmaf(dx1, dx1, fmaf(dy1, dy1, dz1 * dz1)));
                }
                if (u < cnt_s) {
                    const float4 p0 = __ldg(&cp[u]);
                    const float dx0 = qx - p0.x, dy0 = qy - p0.y, dz0 = qz - p0.z;
                    cur = fminf(cur, fmaf(dx0, dx0, fmaf(dy0, dy0, dz0 * dz0)));
                }
            }
        }
        // shell boundary: restore warp-uniform cur
        #pragma unroll
        for (int o = 16; o; o >>= 1)
            cur = fminf(cur, __shfl_xor_sync(full, cur, o));
    }
    if (lane == 0) g_dmin[w] = cur;

    // ---- last-CTA fixed-order reduce (fence -> sync -> vote -> fence) ----
    __threadfence();
    __syncthreads();
    __shared__ unsigned s_last;
    if (threadIdx.x == 0) s_last = (atomicAdd(&g_c2, 1u) == NCTA_Q - 1u);
    __syncthreads();
    if (!s_last) return;
    __threadfence();
    if (threadIdx.x == 0) g_c2 = 0u;

    __shared__ double sm[256];
    const int tid = threadIdx.x;
    double acc = 0.0;
    for (int k = tid; k < 2 * NPTS; k += 256)
        acc += (double)__ldcg(&g_dmin[k]);
    sm[tid] = acc;
    __syncthreads();
    for (int o = 128; o; o >>= 1) {
        if (tid < o) sm[tid] += sm[tid + o];
        __syncthreads();
    }
    if (tid == 0) out[0] = (float)(sm[0] * (1.0 / (double)NPTS));

    // re-zero bucket counts for next graph replay
    int4* gn4 = (int4*)g_n;
    const int4 z4 = make_int4(0, 0, 0, 0);
    for (int k = tid; k < 2 * NC / 4; k += 256) gn4[k] = z4;
}

extern "C" void kernel_launch(void* const* d_in, const int* in_sizes, int n_in,
                              void* d_out, int out_size) {
    const float* p_hat = (const float*)d_in[0];  // [16384,3]
    const float* p     = (const float*)d_in[1];  // [16384,3]
    float* out = (float*)d_out;

    scatter_kernel<<<32, 1024>>>(p_hat, p);
    query_kernel<<<NCTA_Q, 256>>>(p_hat, p, out);
}